// round 2
// baseline (speedup 1.0000x reference)
#include <cuda_runtime.h>

#define THETA 0.5f
#define EPS   1e-5f

__device__ __forceinline__ float fast_tanh(float x) {
    float y;
    asm("tanh.approx.f32 %0, %1;" : "=f"(y) : "f"(x));
    return y;
}

// One CTA per (B,C) plane of 256x256. 256 threads.
// Thread t: patch p = t>>4 (4x4 grid of 64x64 patches), sub = t&15 selects a
// float4 column strip within the patch. Warp = 2 adjacent patches -> each row
// access is 512 contiguous bytes. Phase 1: per-patch (sum,sumsq). One
// __syncthreads. Phase 2: re-read (reverse order, L2-resident), gate, write.
__global__ __launch_bounds__(256) void pmfm_fused(const float* __restrict__ x,
                                                  const float* __restrict__ lw,
                                                  float* __restrict__ out) {
    const int bc  = blockIdx.x;
    const int t   = threadIdx.x;
    const int p   = t >> 4;         // finest patch 0..15
    const int sub = t & 15;         // float4 column within patch
    const int pr  = p >> 2, pc = p & 3;

    const float* plane = x + (size_t)bc * 65536;
    float* oplane      = out + (size_t)bc * 65536;
    const int colf = pc * 64 + sub * 4;   // float column
    const int row0 = pr * 64;

    // ---- Phase 1: per-patch moments ----
    float s = 0.f, ss = 0.f;
#pragma unroll 8
    for (int r = 0; r < 64; ++r) {
        const float4 v = *reinterpret_cast<const float4*>(plane + (size_t)(row0 + r) * 256 + colf);
        s  += (v.x + v.y) + (v.z + v.w);
        ss += v.x * v.x + v.y * v.y + v.z * v.z + v.w * v.w;
    }
    // reduce across the 16 threads of this patch (half-warp segments)
#pragma unroll
    for (int o = 8; o > 0; o >>= 1) {
        s  += __shfl_xor_sync(0xffffffffu, s,  o, 16);
        ss += __shfl_xor_sync(0xffffffffu, ss, o, 16);
    }
    __shared__ float2 st[16];
    if (sub == 0) st[p] = make_float2(s, ss);
    __syncthreads();

    // ---- Coefficients (every thread, from smem broadcast) ----
    // level 2 (finest): own patch
    const float2 f2 = st[p];
    // level 1: 2x2 quadrant of finest patches
    float s1 = 0.f, q1 = 0.f;
    {
        const int qr = pr & ~1, qc = pc & ~1;
#pragma unroll
        for (int dr = 0; dr < 2; ++dr)
#pragma unroll
            for (int dc = 0; dc < 2; ++dc) {
                const float2 v = st[(qr + dr) * 4 + (qc + dc)];
                s1 += v.x; q1 += v.y;
            }
    }
    // level 0: whole plane
    float s0 = 0.f, q0 = 0.f;
#pragma unroll
    for (int i = 0; i < 16; ++i) { s0 += st[i].x; q0 += st[i].y; }

    const float iN2 = 1.f / 4096.f, iN1 = 1.f / 16384.f, iN0 = 1.f / 65536.f;
    const float mu2 = f2.x * iN2; const float v2 = fmaxf(f2.y * iN2 - mu2 * mu2, 0.f);
    const float mu1 = s1  * iN1; const float v1 = fmaxf(q1  * iN1 - mu1 * mu1, 0.f);
    const float mu0 = s0  * iN0; const float v0 = fmaxf(q0  * iN0 - mu0 * mu0, 0.f);

    // sigmoid(z) = 0.5 + 0.5*tanh(z/2); arg = x*a + b with a = 0.5*rsig, b = -mu*a
    const float a2 = 0.5f * rsqrtf(v2 + EPS), b2 = -mu2 * a2;
    const float a1 = 0.5f * rsqrtf(v1 + EPS), b1 = -mu1 * a1;
    const float a0 = 0.5f * rsqrtf(v0 + EPS), b0 = -mu0 * a0;

    // softmax(level_weights); lw[0] pairs with p=2 (finest), lw[2] with p=0
    const float w0 = __ldg(lw + 0), w1 = __ldg(lw + 1), w2 = __ldg(lw + 2);
    const float m  = fmaxf(w0, fmaxf(w1, w2));
    const float e0 = __expf(w0 - m), e1 = __expf(w1 - m), e2 = __expf(w2 - m);
    const float c  = (1.f - THETA) * 0.5f / (e0 + e1 + e2);
    const float cf = c * e0, cm = c * e1, cg = c * e2;
    const float basew = THETA + (1.f - THETA) * 0.5f;

    // ---- Phase 2: re-read (reverse, L2-hot), gate, stream out ----
#pragma unroll 4
    for (int r = 63; r >= 0; --r) {
        const float* pin = plane  + (size_t)(row0 + r) * 256 + colf;
        float*       po  = oplane + (size_t)(row0 + r) * 256 + colf;
        float4 v = __ldcs(reinterpret_cast<const float4*>(pin));
        float4 res;
#define PMFM_DO(comp)                                                         \
        {                                                                     \
            const float xx = v.comp;                                          \
            const float tf = fast_tanh(fmaf(xx, a2, b2));                     \
            const float tm = fast_tanh(fmaf(xx, a1, b1));                     \
            const float tg = fast_tanh(fmaf(xx, a0, b0));                     \
            const float f  = fmaf(cf, tf, fmaf(cm, tm, fmaf(cg, tg, basew))); \
            res.comp = xx * f;                                                \
        }
        PMFM_DO(x) PMFM_DO(y) PMFM_DO(z) PMFM_DO(w)
#undef PMFM_DO
        __stcs(reinterpret_cast<float4*>(po), res);
    }
}

extern "C" void kernel_launch(void* const* d_in, const int* in_sizes, int n_in,
                              void* d_out, int out_size) {
    const float* x;
    const float* lw;
    long nx;
    if (in_sizes[0] >= in_sizes[1]) {
        x = (const float*)d_in[0]; lw = (const float*)d_in[1]; nx = in_sizes[0];
    } else {
        x = (const float*)d_in[1]; lw = (const float*)d_in[0]; nx = in_sizes[1];
    }
    const int nplanes = (int)(nx / 65536);   // B*C = 512 planes of 256x256
    pmfm_fused<<<nplanes, 256>>>(x, lw, (float*)d_out);
}

// round 3
// speedup vs baseline: 1.0941x; 1.0941x over previous
#include <cuda_runtime.h>

#define THETA 0.5f
#define EPS   1e-5f

__device__ __forceinline__ float fast_tanh(float x) {
    float y;
    asm("tanh.approx.f32 %0, %1;" : "=f"(y) : "f"(x));
    return y;
}

// One CTA per (B,C) plane of 256x256. 512 threads = 16 warps; warp w owns the
// 64x64 patch w (4x4 grid). Lane: col16 = lane&15 (float4 column within
// patch), rhalf = lane>>4; rows rhalf+2r, r=0..31 -> 32 float4 per thread.
// Phase 1: per-patch (sum,sumsq) via full-warp shfl. One __syncthreads.
// Phase 2: re-read in reverse (L2-hot), gate, stream out.
__global__ __launch_bounds__(512, 4) void pmfm_fused(const float* __restrict__ x,
                                                     const float* __restrict__ lw,
                                                     float* __restrict__ out) {
    const int bc   = blockIdx.x;
    const int t    = threadIdx.x;
    const int p    = t >> 5;              // warp = finest patch 0..15
    const int lane = t & 31;
    const int pr   = p >> 2, pc = p & 3;

    const float* plane = x + (size_t)bc * 65536;
    float* oplane      = out + (size_t)bc * 65536;
    const int colf  = pc * 64 + (lane & 15) * 4;  // float column
    const int rbase = pr * 64 + (lane >> 4);      // starting row (stride 2)

    // ---- Phase 1: per-patch moments ----
    float s = 0.f, ss = 0.f;
#pragma unroll 8
    for (int r = 0; r < 32; ++r) {
        const float4 v = *reinterpret_cast<const float4*>(
            plane + (size_t)(rbase + 2 * r) * 256 + colf);
        s  += (v.x + v.y) + (v.z + v.w);
        ss += v.x * v.x + v.y * v.y + v.z * v.z + v.w * v.w;
    }
#pragma unroll
    for (int o = 16; o > 0; o >>= 1) {
        s  += __shfl_xor_sync(0xffffffffu, s,  o);
        ss += __shfl_xor_sync(0xffffffffu, ss, o);
    }
    __shared__ float2 st[16];
    if (lane == 0) st[p] = make_float2(s, ss);
    __syncthreads();

    // ---- Coefficients (every thread, from smem broadcast) ----
    const float2 f2 = st[p];                       // level 2: own patch
    float s1 = 0.f, q1 = 0.f;                      // level 1: 2x2 quadrant
    {
        const int qr = pr & ~1, qc = pc & ~1;
#pragma unroll
        for (int dr = 0; dr < 2; ++dr)
#pragma unroll
            for (int dc = 0; dc < 2; ++dc) {
                const float2 v = st[(qr + dr) * 4 + (qc + dc)];
                s1 += v.x; q1 += v.y;
            }
    }
    float s0 = 0.f, q0 = 0.f;                      // level 0: whole plane
#pragma unroll
    for (int i = 0; i < 16; ++i) { s0 += st[i].x; q0 += st[i].y; }

    const float iN2 = 1.f / 4096.f, iN1 = 1.f / 16384.f, iN0 = 1.f / 65536.f;
    const float mu2 = f2.x * iN2; const float v2 = fmaxf(f2.y * iN2 - mu2 * mu2, 0.f);
    const float mu1 = s1  * iN1; const float v1 = fmaxf(q1  * iN1 - mu1 * mu1, 0.f);
    const float mu0 = s0  * iN0; const float v0 = fmaxf(q0  * iN0 - mu0 * mu0, 0.f);

    // sigmoid(z) = 0.5 + 0.5*tanh(z/2); arg = x*a + b, a = 0.5*rsig, b = -mu*a
    const float a2 = 0.5f * rsqrtf(v2 + EPS), b2 = -mu2 * a2;
    const float a1 = 0.5f * rsqrtf(v1 + EPS), b1 = -mu1 * a1;
    const float a0 = 0.5f * rsqrtf(v0 + EPS), b0 = -mu0 * a0;

    // softmax(level_weights); lw[0] pairs with p=2 (finest), lw[2] with p=0
    const float w0 = __ldg(lw + 0), w1 = __ldg(lw + 1), w2 = __ldg(lw + 2);
    const float m  = fmaxf(w0, fmaxf(w1, w2));
    const float e0 = __expf(w0 - m), e1 = __expf(w1 - m), e2 = __expf(w2 - m);
    const float c  = (1.f - THETA) * 0.5f / (e0 + e1 + e2);
    const float cf = c * e0, cm = c * e1, cg = c * e2;
    const float basew = THETA + (1.f - THETA) * 0.5f;

    // ---- Phase 2: re-read (reverse, L2-hot), gate, stream out ----
#pragma unroll 4
    for (int r = 31; r >= 0; --r) {
        const size_t idx = (size_t)(rbase + 2 * r) * 256 + colf;
        float4 v = __ldcs(reinterpret_cast<const float4*>(plane + idx));
        float4 res;
#define PMFM_DO(comp)                                                         \
        {                                                                     \
            const float xx = v.comp;                                          \
            const float tf = fast_tanh(fmaf(xx, a2, b2));                     \
            const float tm = fast_tanh(fmaf(xx, a1, b1));                     \
            const float tg = fast_tanh(fmaf(xx, a0, b0));                     \
            const float f  = fmaf(cf, tf, fmaf(cm, tm, fmaf(cg, tg, basew))); \
            res.comp = xx * f;                                                \
        }
        PMFM_DO(x) PMFM_DO(y) PMFM_DO(z) PMFM_DO(w)
#undef PMFM_DO
        __stcs(reinterpret_cast<float4*>(oplane + idx), res);
    }
}

extern "C" void kernel_launch(void* const* d_in, const int* in_sizes, int n_in,
                              void* d_out, int out_size) {
    const float* x;
    const float* lw;
    long nx;
    if (in_sizes[0] >= in_sizes[1]) {
        x = (const float*)d_in[0]; lw = (const float*)d_in[1]; nx = in_sizes[0];
    } else {
        x = (const float*)d_in[1]; lw = (const float*)d_in[0]; nx = in_sizes[1];
    }
    const int nplanes = (int)(nx / 65536);   // B*C = 512 planes of 256x256
    pmfm_fused<<<nplanes, 512>>>(x, lw, (float*)d_out);
}

// round 4
// speedup vs baseline: 1.1510x; 1.0519x over previous
#include <cuda_runtime.h>
#include <cooperative_groups.h>
namespace cg = cooperative_groups;

#define THETA 0.5f
#define EPS   1e-5f

__device__ __forceinline__ float fast_tanh(float x) {
    float y;
    asm("tanh.approx.f32 %0, %1;" : "=f"(y) : "f"(x));
    return y;
}

// Cluster of 2 CTAs per (B,C) plane. CTA rank r owns rows [128r, 128r+128).
// 256 threads = 8 warps; warp w owns 64x64 patch (prow = 2r + (w>>2), pcol = w&3).
// Phase 1: per-patch (sum,sumsq) -> smem; CTA half-plane total -> smem.
// cluster.sync; fetch peer half-total via DSMEM (one float2). Level-1 quadrants
// never cross the half boundary, so everything else is CTA-local.
// Phase 2: reverse-order L2-hot re-read, gate, streaming store.
__global__ __launch_bounds__(256, 8) __cluster_dims__(2, 1, 1)
void pmfm_fused(const float* __restrict__ x,
                const float* __restrict__ lw,
                float* __restrict__ out) {
    cg::cluster_group cluster = cg::this_cluster();
    const unsigned rank = cluster.block_rank();

    const int bc   = blockIdx.x >> 1;     // plane
    const int t    = threadIdx.x;
    const int w    = t >> 5;              // warp 0..7 = local patch
    const int lane = t & 31;
    const int prow = (int)rank * 2 + (w >> 2);
    const int pcol = w & 3;

    const float* plane = x + (size_t)bc * 65536;
    float* oplane      = out + (size_t)bc * 65536;
    const int colf  = pcol * 64 + (lane & 15) * 4;  // float column
    const int rbase = prow * 64 + (lane >> 4);      // start row (stride 2)

    // ---- Phase 1: per-patch moments ----
    float s = 0.f, ss = 0.f;
#pragma unroll 8
    for (int k = 0; k < 32; ++k) {
        const float4 v = *reinterpret_cast<const float4*>(
            plane + (size_t)(rbase + 2 * k) * 256 + colf);
        s  += (v.x + v.y) + (v.z + v.w);
        ss += v.x * v.x + v.y * v.y + v.z * v.z + v.w * v.w;
    }
#pragma unroll
    for (int o = 16; o > 0; o >>= 1) {
        s  += __shfl_xor_sync(0xffffffffu, s,  o);
        ss += __shfl_xor_sync(0xffffffffu, ss, o);
    }
    __shared__ float2 st[8];        // local 8 patch stats
    __shared__ float2 sh_half;      // this CTA's half-plane total
    if (lane == 0) st[w] = make_float2(s, ss);
    __syncthreads();
    if (t < 8) {                    // warp 0 reduces the 8 patch stats
        float2 v = st[t];
        float hs = v.x, hq = v.y;
#pragma unroll
        for (int o = 4; o > 0; o >>= 1) {
            hs += __shfl_xor_sync(0x000000ffu, hs, o, 8);
            hq += __shfl_xor_sync(0x000000ffu, hq, o, 8);
        }
        if (t == 0) sh_half = make_float2(hs, hq);
    }
    cluster.sync();                 // st + sh_half visible cluster-wide

    // ---- Peer half-plane total via DSMEM (lane 0 loads, warp broadcast) ----
    float ph_s, ph_q;
    {
        float2 ph = make_float2(0.f, 0.f);
        if (lane == 0) {
            const float2* peer = (const float2*)cluster.map_shared_rank(
                (void*)&sh_half, rank ^ 1u);
            ph = *peer;
        }
        ph_s = __shfl_sync(0xffffffffu, ph.x, 0);
        ph_q = __shfl_sync(0xffffffffu, ph.y, 0);
    }
    const float2 own_half = sh_half;
    const float2 f2 = st[w];                        // level 2: own patch
    float s1 = 0.f, q1 = 0.f;                       // level 1: 2x2 quadrant (local)
    {
        const int qc = pcol & ~1;
#pragma unroll
        for (int dr = 0; dr < 2; ++dr)
#pragma unroll
            for (int dc = 0; dc < 2; ++dc) {
                const float2 v = st[dr * 4 + (qc + dc)];
                s1 += v.x; q1 += v.y;
            }
    }
    const float s0 = own_half.x + ph_s;             // level 0: whole plane
    const float q0 = own_half.y + ph_q;
    cluster.sync();                 // all DSMEM reads done before anyone exits

    const float iN2 = 1.f / 4096.f, iN1 = 1.f / 16384.f, iN0 = 1.f / 65536.f;
    const float mu2 = f2.x * iN2; const float v2 = fmaxf(f2.y * iN2 - mu2 * mu2, 0.f);
    const float mu1 = s1  * iN1; const float v1 = fmaxf(q1  * iN1 - mu1 * mu1, 0.f);
    const float mu0 = s0  * iN0; const float v0 = fmaxf(q0  * iN0 - mu0 * mu0, 0.f);

    // sigmoid(z) = 0.5 + 0.5*tanh(z/2); arg = x*a + b, a = 0.5*rsig, b = -mu*a
    const float a2 = 0.5f * rsqrtf(v2 + EPS), b2 = -mu2 * a2;
    const float a1 = 0.5f * rsqrtf(v1 + EPS), b1 = -mu1 * a1;
    const float a0 = 0.5f * rsqrtf(v0 + EPS), b0 = -mu0 * a0;

    // softmax(level_weights); lw[0] pairs with p=2 (finest), lw[2] with p=0
    const float w0 = __ldg(lw + 0), w1 = __ldg(lw + 1), w2 = __ldg(lw + 2);
    const float m  = fmaxf(w0, fmaxf(w1, w2));
    const float e0 = __expf(w0 - m), e1 = __expf(w1 - m), e2 = __expf(w2 - m);
    const float c  = (1.f - THETA) * 0.5f / (e0 + e1 + e2);
    const float cf = c * e0, cm = c * e1, cg_ = c * e2;
    const float basew = THETA + (1.f - THETA) * 0.5f;

    // ---- Phase 2: re-read (reverse, L2-hot), gate, stream out ----
#pragma unroll 4
    for (int k = 31; k >= 0; --k) {
        const size_t idx = (size_t)(rbase + 2 * k) * 256 + colf;
        float4 v = __ldcs(reinterpret_cast<const float4*>(plane + idx));
        float4 res;
#define PMFM_DO(comp)                                                          \
        {                                                                      \
            const float xx = v.comp;                                           \
            const float tf = fast_tanh(fmaf(xx, a2, b2));                      \
            const float tm = fast_tanh(fmaf(xx, a1, b1));                      \
            const float tg = fast_tanh(fmaf(xx, a0, b0));                      \
            const float f  = fmaf(cf, tf, fmaf(cm, tm, fmaf(cg_, tg, basew))); \
            res.comp = xx * f;                                                 \
        }
        PMFM_DO(x) PMFM_DO(y) PMFM_DO(z) PMFM_DO(w)
#undef PMFM_DO
        __stcs(reinterpret_cast<float4*>(oplane + idx), res);
    }
}

extern "C" void kernel_launch(void* const* d_in, const int* in_sizes, int n_in,
                              void* d_out, int out_size) {
    const float* x;
    const float* lw;
    long nx;
    if (in_sizes[0] >= in_sizes[1]) {
        x = (const float*)d_in[0]; lw = (const float*)d_in[1]; nx = in_sizes[0];
    } else {
        x = (const float*)d_in[1]; lw = (const float*)d_in[0]; nx = in_sizes[1];
    }
    const int nplanes = (int)(nx / 65536);   // B*C = 512 planes of 256x256
    pmfm_fused<<<nplanes * 2, 256>>>(x, lw, (float*)d_out);
}

// round 5
// speedup vs baseline: 1.2401x; 1.0774x over previous
#include <cuda_runtime.h>
#include <cooperative_groups.h>
namespace cg = cooperative_groups;

#define THETA 0.5f
#define EPS   1e-5f

__device__ __forceinline__ float fast_tanh(float x) {
    float y;
    asm("tanh.approx.f32 %0, %1;" : "=f"(y) : "f"(x));
    return y;
}

// Cluster of 2 CTAs per (B,C) plane. CTA rank r owns rows [128r, 128r+128).
// 256 threads = 8 warps; warp w owns 64x64 patch (prow = 2r + (w>>2), pcol = w&3).
// Phase 1: batched 4-deep loads, dual accumulators -> per-patch (sum,sumsq).
// cluster.sync; fetch peer half-plane total via DSMEM; arrive early, wait at end.
// Phase 2: reverse-order L2-hot re-read (4-deep batches), gate, streaming store.
__global__ __launch_bounds__(256, 7) __cluster_dims__(2, 1, 1)
void pmfm_fused(const float* __restrict__ x,
                const float* __restrict__ lw,
                float* __restrict__ out) {
    cg::cluster_group cluster = cg::this_cluster();
    const unsigned rank = cluster.block_rank();

    const int bc   = blockIdx.x >> 1;     // plane
    const int t    = threadIdx.x;
    const int w    = t >> 5;              // warp 0..7 = local patch
    const int lane = t & 31;
    const int prow = (int)rank * 2 + (w >> 2);
    const int pcol = w & 3;

    const float* plane = x + (size_t)bc * 65536;
    float* oplane      = out + (size_t)bc * 65536;
    const int colf  = pcol * 64 + (lane & 15) * 4;  // float column
    const int rbase = prow * 64 + (lane >> 4);      // start row (stride 2)

    // float4 view; consecutive k steps 2 rows = 128 float4
    const float4* pin4 = reinterpret_cast<const float4*>(plane + (size_t)rbase * 256 + colf);
    float4*       po4  = reinterpret_cast<float4*>(oplane + (size_t)rbase * 256 + colf);

    // ---- Phase 1: per-patch moments, 4-deep batches, dual accumulators ----
    float sA = 0.f, sB = 0.f, qA = 0.f, qB = 0.f;
#pragma unroll
    for (int c = 0; c < 8; ++c) {
        const float4 va = pin4[(size_t)(4 * c + 0) * 128];
        const float4 vb = pin4[(size_t)(4 * c + 1) * 128];
        const float4 vc = pin4[(size_t)(4 * c + 2) * 128];
        const float4 vd = pin4[(size_t)(4 * c + 3) * 128];
        sA += (va.x + va.y) + (va.z + va.w);
        qA += va.x * va.x + va.y * va.y + va.z * va.z + va.w * va.w;
        sB += (vb.x + vb.y) + (vb.z + vb.w);
        qB += vb.x * vb.x + vb.y * vb.y + vb.z * vb.z + vb.w * vb.w;
        sA += (vc.x + vc.y) + (vc.z + vc.w);
        qA += vc.x * vc.x + vc.y * vc.y + vc.z * vc.z + vc.w * vc.w;
        sB += (vd.x + vd.y) + (vd.z + vd.w);
        qB += vd.x * vd.x + vd.y * vd.y + vd.z * vd.z + vd.w * vd.w;
    }
    float s = sA + sB, ss = qA + qB;
#pragma unroll
    for (int o = 16; o > 0; o >>= 1) {
        s  += __shfl_xor_sync(0xffffffffu, s,  o);
        ss += __shfl_xor_sync(0xffffffffu, ss, o);
    }
    __shared__ float2 st[8];        // local 8 patch stats
    __shared__ float2 sh_half;      // this CTA's half-plane total
    if (lane == 0) st[w] = make_float2(s, ss);
    __syncthreads();
    if (t < 8) {                    // reduce the 8 patch stats
        float2 v = st[t];
        float hs = v.x, hq = v.y;
#pragma unroll
        for (int o = 4; o > 0; o >>= 1) {
            hs += __shfl_xor_sync(0x000000ffu, hs, o, 8);
            hq += __shfl_xor_sync(0x000000ffu, hq, o, 8);
        }
        if (t == 0) sh_half = make_float2(hs, hq);
    }
    cluster.sync();                 // st + sh_half visible cluster-wide

    // ---- Peer half-plane total via DSMEM (lane 0 loads, warp broadcast) ----
    float ph_s, ph_q;
    {
        float2 ph = make_float2(0.f, 0.f);
        if (lane == 0) {
            const float2* peer = (const float2*)cluster.map_shared_rank(
                (void*)&sh_half, rank ^ 1u);
            ph = *peer;
        }
        // shfl forces lane 0's DSMEM load to have completed before any thread
        // proceeds -> safe to 'arrive' afterwards.
        ph_s = __shfl_sync(0xffffffffu, ph.x, 0);
        ph_q = __shfl_sync(0xffffffffu, ph.y, 0);
    }
    const float2 own_half = sh_half;
    const float2 f2 = st[w];                        // level 2: own patch
    float s1 = 0.f, q1 = 0.f;                       // level 1: 2x2 quadrant (local)
    {
        const int qc = pcol & ~1;
#pragma unroll
        for (int dr = 0; dr < 2; ++dr)
#pragma unroll
            for (int dc = 0; dc < 2; ++dc) {
                const float2 v = st[dr * 4 + (qc + dc)];
                s1 += v.x; q1 += v.y;
            }
    }
    const float s0 = own_half.x + ph_s;             // level 0: whole plane
    const float q0 = own_half.y + ph_q;

    // Early arrive: signals "done reading peer smem"; matching wait is at the
    // very end, so the peer-exit guard overlaps with phase 2.
    asm volatile("barrier.cluster.arrive.aligned;" ::: "memory");

    const float iN2 = 1.f / 4096.f, iN1 = 1.f / 16384.f, iN0 = 1.f / 65536.f;
    const float mu2 = f2.x * iN2; const float v2 = fmaxf(f2.y * iN2 - mu2 * mu2, 0.f);
    const float mu1 = s1  * iN1; const float v1 = fmaxf(q1  * iN1 - mu1 * mu1, 0.f);
    const float mu0 = s0  * iN0; const float v0 = fmaxf(q0  * iN0 - mu0 * mu0, 0.f);

    // sigmoid(z) = 0.5 + 0.5*tanh(z/2); arg = x*a + b, a = 0.5*rsig, b = -mu*a
    const float a2 = 0.5f * rsqrtf(v2 + EPS), b2 = -mu2 * a2;
    const float a1 = 0.5f * rsqrtf(v1 + EPS), b1 = -mu1 * a1;
    const float a0 = 0.5f * rsqrtf(v0 + EPS), b0 = -mu0 * a0;

    // softmax(level_weights); lw[0] pairs with p=2 (finest), lw[2] with p=0
    const float w0 = __ldg(lw + 0), w1 = __ldg(lw + 1), w2 = __ldg(lw + 2);
    const float m  = fmaxf(w0, fmaxf(w1, w2));
    const float e0 = __expf(w0 - m), e1 = __expf(w1 - m), e2 = __expf(w2 - m);
    const float c  = (1.f - THETA) * 0.5f / (e0 + e1 + e2);
    const float cf = c * e0, cm = c * e1, cg_ = c * e2;
    const float basew = THETA + (1.f - THETA) * 0.5f;

    // ---- Phase 2: re-read (reverse, L2-hot), 4-deep batches, stream out ----
#pragma unroll
    for (int ch = 7; ch >= 0; --ch) {
        float4 v[4];
#pragma unroll
        for (int j = 0; j < 4; ++j)
            v[j] = __ldcs(&pin4[(size_t)(4 * ch + 3 - j) * 128]);
#pragma unroll
        for (int j = 0; j < 4; ++j) {
            float4 res;
#define PMFM_DO(comp)                                                          \
            {                                                                  \
                const float xx = v[j].comp;                                    \
                const float tf = fast_tanh(fmaf(xx, a2, b2));                  \
                const float tm = fast_tanh(fmaf(xx, a1, b1));                  \
                const float tg = fast_tanh(fmaf(xx, a0, b0));                  \
                const float f  = fmaf(cf, tf, fmaf(cm, tm, fmaf(cg_, tg, basew))); \
                res.comp = xx * f;                                             \
            }
            PMFM_DO(x) PMFM_DO(y) PMFM_DO(z) PMFM_DO(w)
#undef PMFM_DO
            __stcs(&po4[(size_t)(4 * ch + 3 - j) * 128], res);
        }
    }

    // Matching wait for the early arrive: no CTA exits (deallocating its smem)
    // while its peer might still be reading sh_half.
    asm volatile("barrier.cluster.wait.aligned;" ::: "memory");
}

extern "C" void kernel_launch(void* const* d_in, const int* in_sizes, int n_in,
                              void* d_out, int out_size) {
    const float* x;
    const float* lw;
    long nx;
    if (in_sizes[0] >= in_sizes[1]) {
        x = (const float*)d_in[0]; lw = (const float*)d_in[1]; nx = in_sizes[0];
    } else {
        x = (const float*)d_in[1]; lw = (const float*)d_in[0]; nx = in_sizes[1];
    }
    const int nplanes = (int)(nx / 65536);   // B*C = 512 planes of 256x256
    pmfm_fused<<<nplanes * 2, 256>>>(x, lw, (float*)d_out);
}